// round 14
// baseline (speedup 1.0000x reference)
#include <cuda_runtime.h>
#include <math.h>

#define NN    100000
#define IN_C  64
#define HID   128
#define OUT_C 64
#define TILE  32

typedef unsigned long long ull;

// ---------------- scratch (device globals; no allocation allowed) ----------------
__device__ __align__(16) float g_deg[NN];
__device__ __align__(16) float g_agg1[(size_t)NN * IN_C];   // 25.6 MB
__device__ __align__(16) float g_h[(size_t)NN * HID];       // 51.2 MB
__device__ __align__(16) float g_agg2[(size_t)NN * HID];    // 51.2 MB
__device__ int g_is64;

// ---------------- packed f32x2 helpers ----------------
__device__ __forceinline__ ull pack2(float lo, float hi) {
    ull r; asm("mov.b64 %0,{%1,%2};" : "=l"(r) : "f"(lo), "f"(hi)); return r;
}
__device__ __forceinline__ void ffma2(ull& d, ull a, ull b) {
    asm("fma.rn.f32x2 %0,%1,%2,%0;" : "+l"(d) : "l"(a), "l"(b));
}
__device__ __forceinline__ float hadd2(ull v) {
    float lo, hi; asm("mov.b64 {%0,%1},%2;" : "=f"(lo), "=f"(hi) : "l"(v));
    return lo + hi;
}

// ---------------- dtype detect: int64 vs int32 edge_index ----------------
__global__ void detect_kernel(const void* __restrict__ ei) {
    if (blockIdx.x == 0 && threadIdx.x == 0) {
        const unsigned long long* p = (const unsigned long long*)ei;
        int is64 = 1;
#pragma unroll
        for (int i = 0; i < 8; i++)
            if ((p[i] >> 32) != 0ull) is64 = 0;
        g_is64 = is64;
    }
}

// ---------------- zero scratch each launch ----------------
__global__ void zero_kernel() {
    size_t i = (size_t)blockIdx.x * blockDim.x + threadIdx.x;
    size_t stride = (size_t)gridDim.x * blockDim.x;
    float4 z = make_float4(0.f, 0.f, 0.f, 0.f);
    float4* d0 = (float4*)g_deg;
    float4* d1 = (float4*)g_agg1;
    float4* d2 = (float4*)g_agg2;
    for (size_t t = i; t < NN / 4; t += stride) d0[t] = z;
    for (size_t t = i; t < (size_t)NN * IN_C / 4; t += stride) d1[t] = z;
    for (size_t t = i; t < (size_t)NN * HID / 4; t += stride) d2[t] = z;
}

// ---------------- conv1 aggregation: 16 lanes per edge (64 ch) ----------------
__global__ __launch_bounds__(256) void conv1_agg_kernel(
    const float* __restrict__ x, const void* __restrict__ ei, int E)
{
    int tid = blockIdx.x * blockDim.x + threadIdx.x;
    int e = tid >> 4;
    if (e >= E) return;
    int sub = threadIdx.x & 15;
    int is64 = g_is64;
    int src = 0, dst = 0;
    if (sub == 0) {
        if (is64) {
            const long long* p = (const long long*)ei;
            src = (int)p[e]; dst = (int)p[(size_t)E + e];
        } else {
            const int* p = (const int*)ei;
            src = p[e]; dst = p[(size_t)E + e];
        }
    }
    src = __shfl_sync(0xffffffffu, src, 0, 16);
    dst = __shfl_sync(0xffffffffu, dst, 0, 16);

    float4 v = *(const float4*)(x + (size_t)src * IN_C + sub * 4);
    float* d = g_agg1 + (size_t)dst * IN_C + sub * 4;
    asm volatile("red.global.add.v4.f32 [%0], {%1,%2,%3,%4};"
                 :: "l"(d), "f"(v.x), "f"(v.y), "f"(v.z), "f"(v.w) : "memory");
    if (sub == 0) atomicAdd(&g_deg[dst], 1.0f);
}

// ---------------- conv2 aggregation: 32 lanes per edge (128 ch) ----------------
__global__ __launch_bounds__(256) void conv2_agg_kernel(
    const void* __restrict__ ei, int E)
{
    int tid = blockIdx.x * blockDim.x + threadIdx.x;
    int e = tid >> 5;
    if (e >= E) return;
    int ln = threadIdx.x & 31;
    int is64 = g_is64;
    int src = 0, dst = 0;
    if (ln == 0) {
        if (is64) {
            const long long* p = (const long long*)ei;
            src = (int)p[e]; dst = (int)p[(size_t)E + e];
        } else {
            const int* p = (const int*)ei;
            src = p[e]; dst = p[(size_t)E + e];
        }
    }
    src = __shfl_sync(0xffffffffu, src, 0);
    dst = __shfl_sync(0xffffffffu, dst, 0);

    float4 v = *(const float4*)(g_h + (size_t)src * HID + ln * 4);
    float* d = g_agg2 + (size_t)dst * HID + ln * 4;
    asm volatile("red.global.add.v4.f32 [%0], {%1,%2,%3,%4};"
                 :: "l"(d), "f"(v.x), "f"(v.y), "f"(v.z), "f"(v.w) : "memory");
}

// ---------------- conv1 update: h = relu(agg1/deg @ Wl1 + bl1 + x @ Wr1) ----------------
// TILE=32 node smem tile, row = [agg/deg | x] (128 floats).
// 128 threads = 64 ch-slots x 2 node-groups; thread handles channels {l, l+64},
// 16 nodes. Each broadcast LDS.128 feeds 4 ffma2.
__global__ void __launch_bounds__(128, 4) conv1_update_kernel(
    const float* __restrict__ x,
    const float* __restrict__ Wl, const float* __restrict__ bl,
    const float* __restrict__ Wr)
{
    __shared__ __align__(16) float s_in[TILE][2 * IN_C];   // [32][128] = 16 KB
    __shared__ float s_rdeg[TILE];
    int t = threadIdx.x;
    int l = t & 63;                       // channel slot: channels l, l+64
    int ng = t >> 6;                      // node group: nodes ng*16 .. +15
    float b0 = __ldg(&bl[l]);
    float b1 = __ldg(&bl[l + 64]);

    for (int tile = blockIdx.x; tile < NN / TILE; tile += gridDim.x) {
        int base = tile * TILE;
        __syncthreads();                                   // smem reuse guard
        if (t < TILE) s_rdeg[t] = 1.0f / fmaxf(g_deg[base + t], 1.0f);
        __syncthreads();
        // stage 1024 float4 (coalesced), 8 per thread
#pragma unroll
        for (int i = 0; i < 8; i++) {
            int f = t + 128 * i;
            int n = f >> 5, q = f & 31;
            if (q < 16) {
                float4 v = *(const float4*)(g_agg1 + (size_t)(base + n) * IN_C + q * 4);
                float r = s_rdeg[n];
                v.x *= r; v.y *= r; v.z *= r; v.w *= r;
                *(float4*)&s_in[n][q * 4] = v;
            } else {
                *(float4*)&s_in[n][q * 4] =
                    __ldg((const float4*)(x + (size_t)(base + n) * IN_C + (q - 16) * 4));
            }
        }
        __syncthreads();

        ull a0[16], a1[16];
#pragma unroll
        for (int n = 0; n < 16; n++) { a0[n] = 0; a1[n] = 0; }
        const float* s_row = &s_in[ng * 16][0];
        // phase A: (agg/deg) @ Wl — smem cols 0..63
#pragma unroll 4
        for (int ks = 0; ks < 16; ks++) {
            float wa = __ldg(&Wl[(4 * ks + 0) * HID + l]);
            float wb = __ldg(&Wl[(4 * ks + 1) * HID + l]);
            float wc = __ldg(&Wl[(4 * ks + 2) * HID + l]);
            float wd = __ldg(&Wl[(4 * ks + 3) * HID + l]);
            float va = __ldg(&Wl[(4 * ks + 0) * HID + l + 64]);
            float vb = __ldg(&Wl[(4 * ks + 1) * HID + l + 64]);
            float vc = __ldg(&Wl[(4 * ks + 2) * HID + l + 64]);
            float vd = __ldg(&Wl[(4 * ks + 3) * HID + l + 64]);
            ull wA0 = pack2(wa, wb), wB0 = pack2(wc, wd);
            ull wA1 = pack2(va, vb), wB1 = pack2(vc, vd);
#pragma unroll
            for (int n = 0; n < 16; n++) {
                ulonglong2 v = *(const ulonglong2*)(s_row + n * 2 * IN_C + ks * 4);
                ffma2(a0[n], v.x, wA0); ffma2(a0[n], v.y, wB0);
                ffma2(a1[n], v.x, wA1); ffma2(a1[n], v.y, wB1);
            }
        }
        // phase B: x @ Wr — smem cols 64..127
#pragma unroll 4
        for (int ks = 0; ks < 16; ks++) {
            float wa = __ldg(&Wr[(4 * ks + 0) * HID + l]);
            float wb = __ldg(&Wr[(4 * ks + 1) * HID + l]);
            float wc = __ldg(&Wr[(4 * ks + 2) * HID + l]);
            float wd = __ldg(&Wr[(4 * ks + 3) * HID + l]);
            float va = __ldg(&Wr[(4 * ks + 0) * HID + l + 64]);
            float vb = __ldg(&Wr[(4 * ks + 1) * HID + l + 64]);
            float vc = __ldg(&Wr[(4 * ks + 2) * HID + l + 64]);
            float vd = __ldg(&Wr[(4 * ks + 3) * HID + l + 64]);
            ull wA0 = pack2(wa, wb), wB0 = pack2(wc, wd);
            ull wA1 = pack2(va, vb), wB1 = pack2(vc, vd);
#pragma unroll
            for (int n = 0; n < 16; n++) {
                ulonglong2 v = *(const ulonglong2*)(s_row + n * 2 * IN_C + IN_C + ks * 4);
                ffma2(a0[n], v.x, wA0); ffma2(a0[n], v.y, wB0);
                ffma2(a1[n], v.x, wA1); ffma2(a1[n], v.y, wB1);
            }
        }
#pragma unroll
        for (int n = 0; n < 16; n++) {
            size_t row = (size_t)(base + ng * 16 + n) * HID;
            g_h[row + l]      = fmaxf(hadd2(a0[n]) + b0, 0.f);
            g_h[row + l + 64] = fmaxf(hadd2(a1[n]) + b1, 0.f);
        }
    }
}

// ---------------- conv2 update: emb = agg2/deg @ Wl2 + bl2 + h @ Wr2 ----------------
// TILE=32 node smem tile, row = [agg2/deg | h] (256 floats) = 32 KB.
// 128 threads = 32 ch-slots x 4 node-groups; thread handles channels {l, l+32},
// 8 nodes.
__global__ void __launch_bounds__(128, 6) conv2_update_kernel(
    const float* __restrict__ Wl, const float* __restrict__ bl,
    const float* __restrict__ Wr, float* __restrict__ emb)
{
    __shared__ __align__(16) float s_in[TILE][2 * HID];    // [32][256] = 32 KB
    __shared__ float s_rdeg[TILE];
    int t = threadIdx.x;
    int l = t & 31;                       // channel slot: channels l, l+32
    int ng = t >> 5;                      // node group: nodes ng*8 .. +7
    float b0 = __ldg(&bl[l]);
    float b1 = __ldg(&bl[l + 32]);

    for (int tile = blockIdx.x; tile < NN / TILE; tile += gridDim.x) {
        int base = tile * TILE;
        __syncthreads();
        if (t < TILE) s_rdeg[t] = 1.0f / fmaxf(g_deg[base + t], 1.0f);
        __syncthreads();
        // stage 2048 float4, 16 per thread
#pragma unroll
        for (int i = 0; i < 16; i++) {
            int f = t + 128 * i;
            int n = f >> 6, q = f & 63;
            if (q < 32) {
                float4 v = *(const float4*)(g_agg2 + (size_t)(base + n) * HID + q * 4);
                float r = s_rdeg[n];
                v.x *= r; v.y *= r; v.z *= r; v.w *= r;
                *(float4*)&s_in[n][q * 4] = v;
            } else {
                *(float4*)&s_in[n][q * 4] =
                    *(const float4*)(g_h + (size_t)(base + n) * HID + (q - 32) * 4);
            }
        }
        __syncthreads();

        ull a0[8], a1[8];
#pragma unroll
        for (int n = 0; n < 8; n++) { a0[n] = 0; a1[n] = 0; }
        const float* s_row = &s_in[ng * 8][0];
        // phase A: (agg2/deg) @ Wl2 — smem cols 0..127
#pragma unroll 4
        for (int ks = 0; ks < 32; ks++) {
            float wa = __ldg(&Wl[(4 * ks + 0) * OUT_C + l]);
            float wb = __ldg(&Wl[(4 * ks + 1) * OUT_C + l]);
            float wc = __ldg(&Wl[(4 * ks + 2) * OUT_C + l]);
            float wd = __ldg(&Wl[(4 * ks + 3) * OUT_C + l]);
            float va = __ldg(&Wl[(4 * ks + 0) * OUT_C + l + 32]);
            float vb = __ldg(&Wl[(4 * ks + 1) * OUT_C + l + 32]);
            float vc = __ldg(&Wl[(4 * ks + 2) * OUT_C + l + 32]);
            float vd = __ldg(&Wl[(4 * ks + 3) * OUT_C + l + 32]);
            ull wA0 = pack2(wa, wb), wB0 = pack2(wc, wd);
            ull wA1 = pack2(va, vb), wB1 = pack2(vc, vd);
#pragma unroll
            for (int n = 0; n < 8; n++) {
                ulonglong2 v = *(const ulonglong2*)(s_row + n * 2 * HID + ks * 4);
                ffma2(a0[n], v.x, wA0); ffma2(a0[n], v.y, wB0);
                ffma2(a1[n], v.x, wA1); ffma2(a1[n], v.y, wB1);
            }
        }
        // phase B: h @ Wr2 — smem cols 128..255
#pragma unroll 4
        for (int ks = 0; ks < 32; ks++) {
            float wa = __ldg(&Wr[(4 * ks + 0) * OUT_C + l]);
            float wb = __ldg(&Wr[(4 * ks + 1) * OUT_C + l]);
            float wc = __ldg(&Wr[(4 * ks + 2) * OUT_C + l]);
            float wd = __ldg(&Wr[(4 * ks + 3) * OUT_C + l]);
            float va = __ldg(&Wr[(4 * ks + 0) * OUT_C + l + 32]);
            float vb = __ldg(&Wr[(4 * ks + 1) * OUT_C + l + 32]);
            float vc = __ldg(&Wr[(4 * ks + 2) * OUT_C + l + 32]);
            float vd = __ldg(&Wr[(4 * ks + 3) * OUT_C + l + 32]);
            ull wA0 = pack2(wa, wb), wB0 = pack2(wc, wd);
            ull wA1 = pack2(va, vb), wB1 = pack2(vc, vd);
#pragma unroll
            for (int n = 0; n < 8; n++) {
                ulonglong2 v = *(const ulonglong2*)(s_row + n * 2 * HID + HID + ks * 4);
                ffma2(a0[n], v.x, wA0); ffma2(a0[n], v.y, wB0);
                ffma2(a1[n], v.x, wA1); ffma2(a1[n], v.y, wB1);
            }
        }
#pragma unroll
        for (int n = 0; n < 8; n++) {
            size_t row = (size_t)(base + ng * 8 + n) * OUT_C;
            emb[row + l]      = hadd2(a0[n]) + b0;
            emb[row + l + 32] = hadd2(a1[n]) + b1;
        }
    }
}

// ---------------- classifier: sigmoid(relu(relu(emb@Wc1+b)@Wc2+b)@Wc3+b) ----------------
// TILE=32. L1: 64 ch-slots x 2 node-groups (ch {l,l+64}, 16 nodes).
// L2+L3: 32 ch-slots x 4 node-groups (ch {l2,l2+32}, 8 nodes), warp reduce.
__global__ void __launch_bounds__(128, 6) classifier_kernel(
    const float* __restrict__ emb,
    const float* __restrict__ Wc1, const float* __restrict__ bc1,
    const float* __restrict__ Wc2, const float* __restrict__ bc2,
    const float* __restrict__ Wc3, const float* __restrict__ bc3,
    float* __restrict__ probs)
{
    __shared__ __align__(16) float s_e[TILE][OUT_C];       // 8 KB
    __shared__ __align__(16) float s_c1[TILE][HID];        // 16 KB
    __shared__ float s_part[4][8];
    int t = threadIdx.x;
    int l = t & 63;                       // layer-1 slot: ch {l, l+64}
    int ng = t >> 6;                      // 16-node group
    int l2 = t & 31;                      // layer-2 slot: ch {l2, l2+32}
    int ng2 = t >> 5;                     // 8-node group (= warp)
    float b1a = __ldg(&bc1[l]);
    float b1b = __ldg(&bc1[l + 64]);
    float b2a = __ldg(&bc2[l2]);
    float b2b = __ldg(&bc2[l2 + 32]);
    float w3a = __ldg(&Wc3[l2]);
    float w3b = __ldg(&Wc3[l2 + 32]);
    float b3 = __ldg(&bc3[0]);

    for (int tile = blockIdx.x; tile < NN / TILE; tile += gridDim.x) {
        int base = tile * TILE;
        __syncthreads();
        // stage emb tile: 512 float4, 4 per thread
#pragma unroll
        for (int i = 0; i < 4; i++) {
            int f = t + 128 * i;
            int n = f >> 4, q = f & 15;
            *(float4*)&s_e[n][q * 4] =
                *(const float4*)(emb + (size_t)(base + n) * OUT_C + q * 4);
        }
        __syncthreads();

        // layer 1: c1 = relu(emb @ Wc1 + b1)
        {
            ull a0[16], a1[16];
#pragma unroll
            for (int n = 0; n < 16; n++) { a0[n] = 0; a1[n] = 0; }
            const float* s_row = &s_e[ng * 16][0];
#pragma unroll 4
            for (int ks = 0; ks < 16; ks++) {
                float wa = __ldg(&Wc1[(4 * ks + 0) * HID + l]);
                float wb = __ldg(&Wc1[(4 * ks + 1) * HID + l]);
                float wc = __ldg(&Wc1[(4 * ks + 2) * HID + l]);
                float wd = __ldg(&Wc1[(4 * ks + 3) * HID + l]);
                float va = __ldg(&Wc1[(4 * ks + 0) * HID + l + 64]);
                float vb = __ldg(&Wc1[(4 * ks + 1) * HID + l + 64]);
                float vc = __ldg(&Wc1[(4 * ks + 2) * HID + l + 64]);
                float vd = __ldg(&Wc1[(4 * ks + 3) * HID + l + 64]);
                ull wA0 = pack2(wa, wb), wB0 = pack2(wc, wd);
                ull wA1 = pack2(va, vb), wB1 = pack2(vc, vd);
#pragma unroll
                for (int n = 0; n < 16; n++) {
                    ulonglong2 v = *(const ulonglong2*)(s_row + n * OUT_C + ks * 4);
                    ffma2(a0[n], v.x, wA0); ffma2(a0[n], v.y, wB0);
                    ffma2(a1[n], v.x, wA1); ffma2(a1[n], v.y, wB1);
                }
            }
#pragma unroll
            for (int n = 0; n < 16; n++) {
                s_c1[ng * 16 + n][l]      = fmaxf(hadd2(a0[n]) + b1a, 0.f);
                s_c1[ng * 16 + n][l + 64] = fmaxf(hadd2(a1[n]) + b1b, 0.f);
            }
        }
        __syncthreads();

        // layer 2 + 3: thread (l2, 8-node group); sum over 64 ch via 2-per-thread
        // then warp shuffle (32 lanes cover all 64 channels)
        {
            ull p0[8], p1[8];
#pragma unroll
            for (int n = 0; n < 8; n++) { p0[n] = 0; p1[n] = 0; }
            const float* s_row = &s_c1[ng2 * 8][0];
#pragma unroll 4
            for (int ks = 0; ks < 32; ks++) {
                float wa = __ldg(&Wc2[(4 * ks + 0) * 64 + l2]);
                float wb = __ldg(&Wc2[(4 * ks + 1) * 64 + l2]);
                float wc = __ldg(&Wc2[(4 * ks + 2) * 64 + l2]);
                float wd = __ldg(&Wc2[(4 * ks + 3) * 64 + l2]);
                float va = __ldg(&Wc2[(4 * ks + 0) * 64 + l2 + 32]);
                float vb = __ldg(&Wc2[(4 * ks + 1) * 64 + l2 + 32]);
                float vc = __ldg(&Wc2[(4 * ks + 2) * 64 + l2 + 32]);
                float vd = __ldg(&Wc2[(4 * ks + 3) * 64 + l2 + 32]);
                ull wA0 = pack2(wa, wb), wB0 = pack2(wc, wd);
                ull wA1 = pack2(va, vb), wB1 = pack2(vc, vd);
#pragma unroll
                for (int n = 0; n < 8; n++) {
                    ulonglong2 v = *(const ulonglong2*)(s_row + n * HID + ks * 4);
                    ffma2(p0[n], v.x, wA0); ffma2(p0[n], v.y, wB0);
                    ffma2(p1[n], v.x, wA1); ffma2(p1[n], v.y, wB1);
                }
            }
            float y[8];
#pragma unroll
            for (int n = 0; n < 8; n++) {
                y[n] = fmaxf(hadd2(p0[n]) + b2a, 0.f) * w3a
                     + fmaxf(hadd2(p1[n]) + b2b, 0.f) * w3b;
            }
#pragma unroll
            for (int off = 16; off; off >>= 1) {
#pragma unroll
                for (int n = 0; n < 8; n++)
                    y[n] += __shfl_xor_sync(0xffffffffu, y[n], off);
            }
            if (l2 == 0) {
#pragma unroll
                for (int n = 0; n < 8; n++) s_part[ng2][n] = y[n];
            }
        }
        __syncthreads();
        if (t < TILE) {
            float v = s_part[t >> 3][t & 7] + b3;
            probs[base + t] = 1.0f / (1.0f + expf(-v));
        }
    }
}

// ---------------- launch ----------------
extern "C" void kernel_launch(void* const* d_in, const int* in_sizes, int n_in,
                              void* d_out, int out_size)
{
    const float* x   = (const float*)d_in[0];
    const void*  ei  = d_in[1];
    const float* Wl1 = (const float*)d_in[2];
    const float* bl1 = (const float*)d_in[3];
    const float* Wr1 = (const float*)d_in[4];
    const float* Wl2 = (const float*)d_in[5];
    const float* bl2 = (const float*)d_in[6];
    const float* Wr2 = (const float*)d_in[7];
    const float* Wc1 = (const float*)d_in[8];
    const float* bc1 = (const float*)d_in[9];
    const float* Wc2 = (const float*)d_in[10];
    const float* bc2 = (const float*)d_in[11];
    const float* Wc3 = (const float*)d_in[12];
    const float* bc3 = (const float*)d_in[13];
    int E = in_sizes[1] / 2;

    float* out   = (float*)d_out;
    float* emb   = out;                          // [NN, 64]
    float* probs = out + (size_t)NN * OUT_C;     // [NN, 1]

    detect_kernel<<<1, 32>>>(ei);
    zero_kernel<<<2048, 256>>>();
    conv1_agg_kernel<<<(E + 15) / 16, 256>>>(x, ei, E);
    conv1_update_kernel<<<625, 128>>>(x, Wl1, bl1, Wr1);
    conv2_agg_kernel<<<(E + 7) / 8, 256>>>(ei, E);
    conv2_update_kernel<<<625, 128>>>(Wl2, bl2, Wr2, emb);
    classifier_kernel<<<625, 128>>>(emb, Wc1, bc1, Wc2, bc2, Wc3, bc3, probs);
}

// round 15
// speedup vs baseline: 1.3654x; 1.3654x over previous
#include <cuda_runtime.h>
#include <math.h>

#define NN    100000
#define IN_C  64
#define HID   128
#define OUT_C 64
#define TILE  16

typedef unsigned long long ull;

// ---------------- scratch (device globals; no allocation allowed) ----------------
__device__ __align__(16) float g_deg[NN];
__device__ __align__(16) float g_agg1[(size_t)NN * IN_C];   // 25.6 MB
__device__ __align__(16) float g_z[(size_t)NN * OUT_C];     // 25.6 MB  z  = h @ Wl2
__device__ __align__(16) float g_hr[(size_t)NN * OUT_C];    // 25.6 MB  hr = h @ Wr2
__device__ __align__(16) float g_aggz[(size_t)NN * OUT_C];  // 25.6 MB  agg of z
__device__ int g_is64;

// ---------------- packed f32x2 helpers ----------------
__device__ __forceinline__ ull pack2(float lo, float hi) {
    ull r; asm("mov.b64 %0,{%1,%2};" : "=l"(r) : "f"(lo), "f"(hi)); return r;
}
__device__ __forceinline__ void ffma2(ull& d, ull a, ull b) {
    asm("fma.rn.f32x2 %0,%1,%2,%0;" : "+l"(d) : "l"(a), "l"(b));
}
__device__ __forceinline__ float hadd2(ull v) {
    float lo, hi; asm("mov.b64 {%0,%1},%2;" : "=f"(lo), "=f"(hi) : "l"(v));
    return lo + hi;
}

// ---------------- dtype detect: int64 vs int32 edge_index ----------------
__global__ void detect_kernel(const void* __restrict__ ei) {
    if (blockIdx.x == 0 && threadIdx.x == 0) {
        const unsigned long long* p = (const unsigned long long*)ei;
        int is64 = 1;
#pragma unroll
        for (int i = 0; i < 8; i++)
            if ((p[i] >> 32) != 0ull) is64 = 0;
        g_is64 = is64;
    }
}

// ---------------- zero scratch each launch (deg + agg1 + aggz = 51.6 MB) --------
__global__ void zero_kernel() {
    size_t i = (size_t)blockIdx.x * blockDim.x + threadIdx.x;
    size_t stride = (size_t)gridDim.x * blockDim.x;
    float4 z = make_float4(0.f, 0.f, 0.f, 0.f);
    float4* d0 = (float4*)g_deg;
    float4* d1 = (float4*)g_agg1;
    float4* d2 = (float4*)g_aggz;
    for (size_t t = i; t < NN / 4; t += stride) d0[t] = z;
    for (size_t t = i; t < (size_t)NN * IN_C / 4; t += stride) d1[t] = z;
    for (size_t t = i; t < (size_t)NN * OUT_C / 4; t += stride) d2[t] = z;
}

// ---------------- conv1 aggregation: 16 lanes per edge (64 ch) + degree ---------
__global__ __launch_bounds__(256) void conv1_agg_kernel(
    const float* __restrict__ x, const void* __restrict__ ei, int E)
{
    int tid = blockIdx.x * blockDim.x + threadIdx.x;
    int e = tid >> 4;
    if (e >= E) return;
    int sub = threadIdx.x & 15;
    int is64 = g_is64;
    int src = 0, dst = 0;
    if (sub == 0) {
        if (is64) {
            const long long* p = (const long long*)ei;
            src = (int)p[e]; dst = (int)p[(size_t)E + e];
        } else {
            const int* p = (const int*)ei;
            src = p[e]; dst = p[(size_t)E + e];
        }
    }
    src = __shfl_sync(0xffffffffu, src, 0, 16);
    dst = __shfl_sync(0xffffffffu, dst, 0, 16);

    float4 v = *(const float4*)(x + (size_t)src * IN_C + sub * 4);
    float* d = g_agg1 + (size_t)dst * IN_C + sub * 4;
    asm volatile("red.global.add.v4.f32 [%0], {%1,%2,%3,%4};"
                 :: "l"(d), "f"(v.x), "f"(v.y), "f"(v.z), "f"(v.w) : "memory");
    if (sub == 0) atomicAdd(&g_deg[dst], 1.0f);
}

// ---------------- conv2 aggregation on z: 16 lanes per edge (64 ch) -------------
__global__ __launch_bounds__(256) void conv2_agg_kernel(
    const void* __restrict__ ei, int E)
{
    int tid = blockIdx.x * blockDim.x + threadIdx.x;
    int e = tid >> 4;
    if (e >= E) return;
    int sub = threadIdx.x & 15;
    int is64 = g_is64;
    int src = 0, dst = 0;
    if (sub == 0) {
        if (is64) {
            const long long* p = (const long long*)ei;
            src = (int)p[e]; dst = (int)p[(size_t)E + e];
        } else {
            const int* p = (const int*)ei;
            src = p[e]; dst = p[(size_t)E + e];
        }
    }
    src = __shfl_sync(0xffffffffu, src, 0, 16);
    dst = __shfl_sync(0xffffffffu, dst, 0, 16);

    float4 v = *(const float4*)(g_z + (size_t)src * OUT_C + sub * 4);
    float* d = g_aggz + (size_t)dst * OUT_C + sub * 4;
    asm volatile("red.global.add.v4.f32 [%0], {%1,%2,%3,%4};"
                 :: "l"(d), "f"(v.x), "f"(v.y), "f"(v.z), "f"(v.w) : "memory");
}

// ---------------- fused update ----------------
// Phase 1 (R13-proven shape): h = relu(agg1/deg @ Wl1 + bl1 + x @ Wr1) into smem.
// Phase 2: z = h @ Wl2, hr = h @ Wr2 (the block owns all 128 ch of its 16 nodes,
// so h never touches global memory). Scatter-ready 64-ch z replaces 128-ch h.
__global__ void __launch_bounds__(128, 6) fused_update_kernel(
    const float* __restrict__ x,
    const float* __restrict__ Wl1, const float* __restrict__ bl1,
    const float* __restrict__ Wr1,
    const float* __restrict__ Wl2, const float* __restrict__ Wr2)
{
    __shared__ __align__(16) float s_in[TILE][2 * IN_C];   // [16][128] = 8 KB
    __shared__ float s_rdeg[TILE];
    int t = threadIdx.x;                 // phase1: out channel 0..127
    float b = __ldg(&bl1[t]);
    int c = t & 63;                      // phase2: output column
    const float* W2 = (t < 64) ? Wl2 : Wr2;
    float* out2 = (t < 64) ? g_z : g_hr;

    for (int tile = blockIdx.x; tile < NN / TILE; tile += gridDim.x) {
        int base = tile * TILE;
        __syncthreads();                                   // smem reuse guard
        if (t < TILE) s_rdeg[t] = 1.0f / fmaxf(g_deg[base + t], 1.0f);
        __syncthreads();
        // stage 512 float4 (coalesced), 4 per thread: [agg1/deg | x]
#pragma unroll
        for (int i = 0; i < 4; i++) {
            int f = t + 128 * i;
            int n = f >> 5, q = f & 31;
            if (q < 16) {
                float4 v = *(const float4*)(g_agg1 + (size_t)(base + n) * IN_C + q * 4);
                float r = s_rdeg[n];
                v.x *= r; v.y *= r; v.z *= r; v.w *= r;
                *(float4*)&s_in[n][q * 4] = v;
            } else {
                *(float4*)&s_in[n][q * 4] =
                    __ldg((const float4*)(x + (size_t)(base + n) * IN_C + (q - 16) * 4));
            }
        }
        __syncthreads();

        // ---- phase 1: h[n][t] ----
        float hv[TILE];
        {
            ull acc[TILE];
#pragma unroll
            for (int n = 0; n < TILE; n++) acc[n] = 0;
#pragma unroll 4
            for (int ks = 0; ks < 16; ks++) {
                float w0 = __ldg(&Wl1[(4 * ks + 0) * HID + t]);
                float w1 = __ldg(&Wl1[(4 * ks + 1) * HID + t]);
                float w2 = __ldg(&Wl1[(4 * ks + 2) * HID + t]);
                float w3 = __ldg(&Wl1[(4 * ks + 3) * HID + t]);
                ull wA = pack2(w0, w1), wB = pack2(w2, w3);
#pragma unroll
                for (int n = 0; n < TILE; n++) {
                    ulonglong2 v = *(const ulonglong2*)&s_in[n][ks * 4];
                    ffma2(acc[n], v.x, wA); ffma2(acc[n], v.y, wB);
                }
            }
#pragma unroll 4
            for (int ks = 0; ks < 16; ks++) {
                float w0 = __ldg(&Wr1[(4 * ks + 0) * HID + t]);
                float w1 = __ldg(&Wr1[(4 * ks + 1) * HID + t]);
                float w2 = __ldg(&Wr1[(4 * ks + 2) * HID + t]);
                float w3 = __ldg(&Wr1[(4 * ks + 3) * HID + t]);
                ull wA = pack2(w0, w1), wB = pack2(w2, w3);
#pragma unroll
                for (int n = 0; n < TILE; n++) {
                    ulonglong2 v = *(const ulonglong2*)&s_in[n][IN_C + ks * 4];
                    ffma2(acc[n], v.x, wA); ffma2(acc[n], v.y, wB);
                }
            }
#pragma unroll
            for (int n = 0; n < TILE; n++)
                hv[n] = fmaxf(hadd2(acc[n]) + b, 0.f);
        }
        __syncthreads();                  // all phase-1 reads of s_in done
#pragma unroll
        for (int n = 0; n < TILE; n++) s_in[n][t] = hv[n];   // h tile into smem
        __syncthreads();

        // ---- phase 2: z/hr[n][c] = h[n][:] @ W2[:, c] ----
        {
            ull acc[TILE];
#pragma unroll
            for (int n = 0; n < TILE; n++) acc[n] = 0;
#pragma unroll 4
            for (int ks = 0; ks < 32; ks++) {              // K = 128
                float w0 = __ldg(&W2[(4 * ks + 0) * OUT_C + c]);
                float w1 = __ldg(&W2[(4 * ks + 1) * OUT_C + c]);
                float w2 = __ldg(&W2[(4 * ks + 2) * OUT_C + c]);
                float w3 = __ldg(&W2[(4 * ks + 3) * OUT_C + c]);
                ull wA = pack2(w0, w1), wB = pack2(w2, w3);
#pragma unroll
                for (int n = 0; n < TILE; n++) {
                    ulonglong2 v = *(const ulonglong2*)&s_in[n][ks * 4];
                    ffma2(acc[n], v.x, wA); ffma2(acc[n], v.y, wB);
                }
            }
#pragma unroll
            for (int n = 0; n < TILE; n++)
                out2[(size_t)(base + n) * OUT_C + c] = hadd2(acc[n]);
        }
    }
}

// ---------------- classifier (fused emb construction) ----------------
// Staging computes emb = aggz/deg + bl2 + hr, writes it to d_out, then runs the
// MLP (R13-proven shape): L1 thread = hidden ch, L2+L3 (c, node-group) + reduce.
__global__ void __launch_bounds__(128, 6) classifier_kernel(
    const float* __restrict__ bl2,
    const float* __restrict__ Wc1, const float* __restrict__ bc1,
    const float* __restrict__ Wc2, const float* __restrict__ bc2,
    const float* __restrict__ Wc3, const float* __restrict__ bc3,
    float* __restrict__ emb, float* __restrict__ probs)
{
    __shared__ __align__(16) float s_e[TILE][OUT_C];       // 4 KB
    __shared__ __align__(16) float s_c1[TILE][HID];        // 8 KB
    __shared__ float s_rdeg[TILE];
    __shared__ float s_part[4][8];
    int t = threadIdx.x;
    int c = t & 63;
    int nb = (t >> 6) * 8;
    int wid = t >> 5;
    float b1 = __ldg(&bc1[t]);
    float b2 = __ldg(&bc2[c]);
    float w3c = __ldg(&Wc3[c]);
    float b3 = __ldg(&bc3[0]);

    for (int tile = blockIdx.x; tile < NN / TILE; tile += gridDim.x) {
        int base = tile * TILE;
        __syncthreads();
        if (t < TILE) s_rdeg[t] = 1.0f / fmaxf(g_deg[base + t], 1.0f);
        __syncthreads();
        // stage emb = aggz/deg + bl2 + hr : 256 float4, 2 per thread; also write out
#pragma unroll
        for (int i = 0; i < 2; i++) {
            int f = t + 128 * i;
            int n = f >> 4, q = f & 15;
            float4 az = *(const float4*)(g_aggz + (size_t)(base + n) * OUT_C + q * 4);
            float4 hr = *(const float4*)(g_hr + (size_t)(base + n) * OUT_C + q * 4);
            float4 bv = __ldg((const float4*)(bl2 + q * 4));
            float r = s_rdeg[n];
            float4 e;
            e.x = az.x * r + bv.x + hr.x;
            e.y = az.y * r + bv.y + hr.y;
            e.z = az.z * r + bv.z + hr.z;
            e.w = az.w * r + bv.w + hr.w;
            *(float4*)&s_e[n][q * 4] = e;
            *(float4*)(emb + (size_t)(base + n) * OUT_C + q * 4) = e;
        }
        __syncthreads();

        // layer 1: c1 = relu(emb @ Wc1 + b1), thread t = hidden channel
        {
            ull acc[TILE];
#pragma unroll
            for (int n = 0; n < TILE; n++) acc[n] = 0;
#pragma unroll 4
            for (int ks = 0; ks < 16; ks++) {
                float w0 = __ldg(&Wc1[(4 * ks + 0) * HID + t]);
                float w1 = __ldg(&Wc1[(4 * ks + 1) * HID + t]);
                float w2 = __ldg(&Wc1[(4 * ks + 2) * HID + t]);
                float w3 = __ldg(&Wc1[(4 * ks + 3) * HID + t]);
                ull wA = pack2(w0, w1), wB = pack2(w2, w3);
#pragma unroll
                for (int n = 0; n < TILE; n++) {
                    ulonglong2 v = *(const ulonglong2*)&s_e[n][ks * 4];
                    ffma2(acc[n], v.x, wA); ffma2(acc[n], v.y, wB);
                }
            }
#pragma unroll
            for (int n = 0; n < TILE; n++)
                s_c1[n][t] = fmaxf(hadd2(acc[n]) + b1, 0.f);
        }
        __syncthreads();

        // layer 2 + 3: thread (c, node-group), 8 nodes
        {
            ull p[8];
#pragma unroll
            for (int n = 0; n < 8; n++) p[n] = 0;
#pragma unroll 4
            for (int ks = 0; ks < 32; ks++) {
                float w0 = __ldg(&Wc2[(4 * ks + 0) * 64 + c]);
                float w1 = __ldg(&Wc2[(4 * ks + 1) * 64 + c]);
                float w2 = __ldg(&Wc2[(4 * ks + 2) * 64 + c]);
                float w3 = __ldg(&Wc2[(4 * ks + 3) * 64 + c]);
                ull wA = pack2(w0, w1), wB = pack2(w2, w3);
#pragma unroll
                for (int n = 0; n < 8; n++) {
                    ulonglong2 v = *(const ulonglong2*)&s_c1[nb + n][ks * 4];
                    ffma2(p[n], v.x, wA); ffma2(p[n], v.y, wB);
                }
            }
            float y[8];
#pragma unroll
            for (int n = 0; n < 8; n++)
                y[n] = fmaxf(hadd2(p[n]) + b2, 0.f) * w3c;
#pragma unroll
            for (int off = 16; off; off >>= 1) {
#pragma unroll
                for (int n = 0; n < 8; n++)
                    y[n] += __shfl_xor_sync(0xffffffffu, y[n], off);
            }
            if ((t & 31) == 0) {
#pragma unroll
                for (int n = 0; n < 8; n++) s_part[wid][n] = y[n];
            }
        }
        __syncthreads();
        if (t < TILE) {
            int n = t;
            float v = (n < 8) ? (s_part[0][n] + s_part[1][n])
                              : (s_part[2][n - 8] + s_part[3][n - 8]);
            v += b3;
            probs[base + n] = 1.0f / (1.0f + expf(-v));
        }
    }
}

// ---------------- launch ----------------
extern "C" void kernel_launch(void* const* d_in, const int* in_sizes, int n_in,
                              void* d_out, int out_size)
{
    const float* x   = (const float*)d_in[0];
    const void*  ei  = d_in[1];
    const float* Wl1 = (const float*)d_in[2];
    const float* bl1 = (const float*)d_in[3];
    const float* Wr1 = (const float*)d_in[4];
    const float* Wl2 = (const float*)d_in[5];
    const float* bl2 = (const float*)d_in[6];
    const float* Wr2 = (const float*)d_in[7];
    const float* Wc1 = (const float*)d_in[8];
    const float* bc1 = (const float*)d_in[9];
    const float* Wc2 = (const float*)d_in[10];
    const float* bc2 = (const float*)d_in[11];
    const float* Wc3 = (const float*)d_in[12];
    const float* bc3 = (const float*)d_in[13];
    int E = in_sizes[1] / 2;

    float* out   = (float*)d_out;
    float* emb   = out;                          // [NN, 64]
    float* probs = out + (size_t)NN * OUT_C;     // [NN, 1]

    detect_kernel<<<1, 32>>>(ei);
    zero_kernel<<<2048, 256>>>();
    conv1_agg_kernel<<<(E + 15) / 16, 256>>>(x, ei, E);
    fused_update_kernel<<<888, 128>>>(x, Wl1, bl1, Wr1, Wl2, Wr2);
    conv2_agg_kernel<<<(E + 15) / 16, 256>>>(ei, E);
    classifier_kernel<<<888, 128>>>(bl2, Wc1, bc1, Wc2, bc2, Wc3, bc3, emb, probs);
}

// round 17
// speedup vs baseline: 1.4863x; 1.0885x over previous
#include <cuda_runtime.h>
#include <math.h>

#define NN    100000
#define IN_C  64
#define HID   128
#define OUT_C 64
#define TILE  16

typedef unsigned long long ull;

// ---------------- scratch (device globals; no allocation allowed) ----------------
__device__ __align__(16) float g_deg[NN];
__device__ __align__(16) float g_agg1[(size_t)NN * IN_C];   // 25.6 MB
__device__ __align__(16) float g_z[(size_t)NN * OUT_C];     // 25.6 MB  z  = h @ Wl2
__device__ __align__(16) float g_hr[(size_t)NN * OUT_C];    // 25.6 MB  hr = h @ Wr2
__device__ __align__(16) float g_aggz[(size_t)NN * OUT_C];  // 25.6 MB  agg of z
__device__ int g_is64;

// ---------------- packed f32x2 helpers ----------------
__device__ __forceinline__ ull pack2(float lo, float hi) {
    ull r; asm("mov.b64 %0,{%1,%2};" : "=l"(r) : "f"(lo), "f"(hi)); return r;
}
__device__ __forceinline__ void ffma2(ull& d, ull a, ull b) {
    asm("fma.rn.f32x2 %0,%1,%2,%0;" : "+l"(d) : "l"(a), "l"(b));
}
__device__ __forceinline__ float hadd2(ull v) {
    float lo, hi; asm("mov.b64 {%0,%1},%2;" : "=f"(lo), "=f"(hi) : "l"(v));
    return lo + hi;
}

// ---------------- dtype detect: int64 vs int32 edge_index ----------------
__global__ void detect_kernel(const void* __restrict__ ei) {
    if (blockIdx.x == 0 && threadIdx.x == 0) {
        const unsigned long long* p = (const unsigned long long*)ei;
        int is64 = 1;
#pragma unroll
        for (int i = 0; i < 8; i++)
            if ((p[i] >> 32) != 0ull) is64 = 0;
        g_is64 = is64;
    }
}

// ---------------- zero scratch each launch (deg + agg1 + aggz = 51.6 MB) --------
__global__ void zero_kernel() {
    size_t i = (size_t)blockIdx.x * blockDim.x + threadIdx.x;
    size_t stride = (size_t)gridDim.x * blockDim.x;
    float4 z = make_float4(0.f, 0.f, 0.f, 0.f);
    float4* d0 = (float4*)g_deg;
    float4* d1 = (float4*)g_agg1;
    float4* d2 = (float4*)g_aggz;
    for (size_t t = i; t < NN / 4; t += stride) d0[t] = z;
    for (size_t t = i; t < (size_t)NN * IN_C / 4; t += stride) d1[t] = z;
    for (size_t t = i; t < (size_t)NN * OUT_C / 4; t += stride) d2[t] = z;
}

// ---------------- conv1 aggregation: 16 lanes per edge (64 ch) + degree ---------
__global__ __launch_bounds__(256) void conv1_agg_kernel(
    const float* __restrict__ x, const void* __restrict__ ei, int E)
{
    int tid = blockIdx.x * blockDim.x + threadIdx.x;
    int e = tid >> 4;
    if (e >= E) return;
    int sub = threadIdx.x & 15;
    int is64 = g_is64;
    int src = 0, dst = 0;
    if (sub == 0) {
        if (is64) {
            const long long* p = (const long long*)ei;
            src = (int)p[e]; dst = (int)p[(size_t)E + e];
        } else {
            const int* p = (const int*)ei;
            src = p[e]; dst = p[(size_t)E + e];
        }
    }
    src = __shfl_sync(0xffffffffu, src, 0, 16);
    dst = __shfl_sync(0xffffffffu, dst, 0, 16);

    float4 v = *(const float4*)(x + (size_t)src * IN_C + sub * 4);
    float* d = g_agg1 + (size_t)dst * IN_C + sub * 4;
    asm volatile("red.global.add.v4.f32 [%0], {%1,%2,%3,%4};"
                 :: "l"(d), "f"(v.x), "f"(v.y), "f"(v.z), "f"(v.w) : "memory");
    if (sub == 0) atomicAdd(&g_deg[dst], 1.0f);
}

// ---------------- conv2 aggregation on z: 16 lanes per edge (64 ch) -------------
__global__ __launch_bounds__(256) void conv2_agg_kernel(
    const void* __restrict__ ei, int E)
{
    int tid = blockIdx.x * blockDim.x + threadIdx.x;
    int e = tid >> 4;
    if (e >= E) return;
    int sub = threadIdx.x & 15;
    int is64 = g_is64;
    int src = 0, dst = 0;
    if (sub == 0) {
        if (is64) {
            const long long* p = (const long long*)ei;
            src = (int)p[e]; dst = (int)p[(size_t)E + e];
        } else {
            const int* p = (const int*)ei;
            src = p[e]; dst = p[(size_t)E + e];
        }
    }
    src = __shfl_sync(0xffffffffu, src, 0, 16);
    dst = __shfl_sync(0xffffffffu, dst, 0, 16);

    float4 v = *(const float4*)(g_z + (size_t)src * OUT_C + sub * 4);
    float* d = g_aggz + (size_t)dst * OUT_C + sub * 4;
    asm volatile("red.global.add.v4.f32 [%0], {%1,%2,%3,%4};"
                 :: "l"(d), "f"(v.x), "f"(v.y), "f"(v.z), "f"(v.w) : "memory");
}

// ---------------- fused update ----------------
// Phase 1: h = relu(agg1/deg @ Wl1 + bl1 + x @ Wr1) into smem.
//   8n x 2c microtile: thread -> ch {l, l+64}, node-half ng (8 nodes). 16 acc.
// Phase 2: z = h @ Wl2, hr = h @ Wr2.
//   thread -> (matrix m, ch {c2, c2+32}, node-half nh). 16 acc.
__global__ void __launch_bounds__(128, 6) fused_update_kernel(
    const float* __restrict__ x,
    const float* __restrict__ Wl1, const float* __restrict__ bl1,
    const float* __restrict__ Wr1,
    const float* __restrict__ Wl2, const float* __restrict__ Wr2)
{
    __shared__ __align__(16) float s_in[TILE][2 * IN_C];   // [16][128] = 8 KB
    __shared__ float s_rdeg[TILE];
    int t = threadIdx.x;
    int l = t & 63;                       // phase1 ch pair {l, l+64}
    int ng = t >> 6;                      // phase1 node half (8 nodes)
    float b0 = __ldg(&bl1[l]);
    float b1 = __ldg(&bl1[l + 64]);
    // phase2 mapping: m = t>>6 (0:z via Wl2, 1:hr via Wr2), nh = (t>>5)&1, c2 = t&31
    int m = t >> 6;
    int nh = (t >> 5) & 1;
    int c2 = t & 31;
    const float* W2 = m ? Wr2 : Wl2;
    float* out2 = m ? g_hr : g_z;

    for (int tile = blockIdx.x; tile < NN / TILE; tile += gridDim.x) {
        int base = tile * TILE;
        __syncthreads();                                   // smem reuse guard
        if (t < TILE) s_rdeg[t] = 1.0f / fmaxf(g_deg[base + t], 1.0f);
        __syncthreads();
        // stage 512 float4 (coalesced), 4 per thread: [agg1/deg | x]
#pragma unroll
        for (int i = 0; i < 4; i++) {
            int f = t + 128 * i;
            int n = f >> 5, q = f & 31;
            if (q < 16) {
                float4 v = *(const float4*)(g_agg1 + (size_t)(base + n) * IN_C + q * 4);
                float r = s_rdeg[n];
                v.x *= r; v.y *= r; v.z *= r; v.w *= r;
                *(float4*)&s_in[n][q * 4] = v;
            } else {
                *(float4*)&s_in[n][q * 4] =
                    __ldg((const float4*)(x + (size_t)(base + n) * IN_C + (q - 16) * 4));
            }
        }
        __syncthreads();

        // ---- phase 1: h for 8 nodes x 2 channels ----
        float hv0[8], hv1[8];
        {
            ull a0[8], a1[8];
#pragma unroll
            for (int n = 0; n < 8; n++) { a0[n] = 0; a1[n] = 0; }
            const float* s_row = &s_in[ng * 8][0];
            // phase A: (agg/deg) @ Wl1 — smem cols 0..63
#pragma unroll 4
            for (int ks = 0; ks < 16; ks++) {
                float wa = __ldg(&Wl1[(4 * ks + 0) * HID + l]);
                float wb = __ldg(&Wl1[(4 * ks + 1) * HID + l]);
                float wc = __ldg(&Wl1[(4 * ks + 2) * HID + l]);
                float wd = __ldg(&Wl1[(4 * ks + 3) * HID + l]);
                float va = __ldg(&Wl1[(4 * ks + 0) * HID + l + 64]);
                float vb = __ldg(&Wl1[(4 * ks + 1) * HID + l + 64]);
                float vc = __ldg(&Wl1[(4 * ks + 2) * HID + l + 64]);
                float vd = __ldg(&Wl1[(4 * ks + 3) * HID + l + 64]);
                ull wA0 = pack2(wa, wb), wB0 = pack2(wc, wd);
                ull wA1 = pack2(va, vb), wB1 = pack2(vc, vd);
#pragma unroll
                for (int n = 0; n < 8; n++) {
                    ulonglong2 v = *(const ulonglong2*)(s_row + n * 2 * IN_C + ks * 4);
                    ffma2(a0[n], v.x, wA0); ffma2(a0[n], v.y, wB0);
                    ffma2(a1[n], v.x, wA1); ffma2(a1[n], v.y, wB1);
                }
            }
            // phase B: x @ Wr1 — smem cols 64..127
#pragma unroll 4
            for (int ks = 0; ks < 16; ks++) {
                float wa = __ldg(&Wr1[(4 * ks + 0) * HID + l]);
                float wb = __ldg(&Wr1[(4 * ks + 1) * HID + l]);
                float wc = __ldg(&Wr1[(4 * ks + 2) * HID + l]);
                float wd = __ldg(&Wr1[(4 * ks + 3) * HID + l]);
                float va = __ldg(&Wr1[(4 * ks + 0) * HID + l + 64]);
                float vb = __ldg(&Wr1[(4 * ks + 1) * HID + l + 64]);
                float vc = __ldg(&Wr1[(4 * ks + 2) * HID + l + 64]);
                float vd = __ldg(&Wr1[(4 * ks + 3) * HID + l + 64]);
                ull wA0 = pack2(wa, wb), wB0 = pack2(wc, wd);
                ull wA1 = pack2(va, vb), wB1 = pack2(vc, vd);
#pragma unroll
                for (int n = 0; n < 8; n++) {
                    ulonglong2 v = *(const ulonglong2*)(s_row + n * 2 * IN_C + IN_C + ks * 4);
                    ffma2(a0[n], v.x, wA0); ffma2(a0[n], v.y, wB0);
                    ffma2(a1[n], v.x, wA1); ffma2(a1[n], v.y, wB1);
                }
            }
#pragma unroll
            for (int n = 0; n < 8; n++) {
                hv0[n] = fmaxf(hadd2(a0[n]) + b0, 0.f);
                hv1[n] = fmaxf(hadd2(a1[n]) + b1, 0.f);
            }
        }
        __syncthreads();                  // all phase-1 reads of s_in done
#pragma unroll
        for (int n = 0; n < 8; n++) {
            s_in[ng * 8 + n][l]      = hv0[n];
            s_in[ng * 8 + n][l + 64] = hv1[n];
        }
        __syncthreads();

        // ---- phase 2: z/hr for 8 nodes x 2 channels, K=128 ----
        {
            ull a0[8], a1[8];
#pragma unroll
            for (int n = 0; n < 8; n++) { a0[n] = 0; a1[n] = 0; }
            const float* s_row = &s_in[nh * 8][0];
#pragma unroll 4
            for (int ks = 0; ks < 32; ks++) {
                float wa = __ldg(&W2[(4 * ks + 0) * OUT_C + c2]);
                float wb = __ldg(&W2[(4 * ks + 1) * OUT_C + c2]);
                float wc = __ldg(&W2[(4 * ks + 2) * OUT_C + c2]);
                float wd = __ldg(&W2[(4 * ks + 3) * OUT_C + c2]);
                float va = __ldg(&W2[(4 * ks + 0) * OUT_C + c2 + 32]);
                float vb = __ldg(&W2[(4 * ks + 1) * OUT_C + c2 + 32]);
                float vc = __ldg(&W2[(4 * ks + 2) * OUT_C + c2 + 32]);
                float vd = __ldg(&W2[(4 * ks + 3) * OUT_C + c2 + 32]);
                ull wA0 = pack2(wa, wb), wB0 = pack2(wc, wd);
                ull wA1 = pack2(va, vb), wB1 = pack2(vc, vd);
#pragma unroll
                for (int n = 0; n < 8; n++) {
                    ulonglong2 v = *(const ulonglong2*)(s_row + n * 2 * IN_C + ks * 4);
                    ffma2(a0[n], v.x, wA0); ffma2(a0[n], v.y, wB0);
                    ffma2(a1[n], v.x, wA1); ffma2(a1[n], v.y, wB1);
                }
            }
#pragma unroll
            for (int n = 0; n < 8; n++) {
                size_t row = (size_t)(base + nh * 8 + n) * OUT_C;
                out2[row + c2]      = hadd2(a0[n]);
                out2[row + c2 + 32] = hadd2(a1[n]);
            }
        }
    }
}

// ---------------- classifier (fused emb construction) ----------------
// Staging computes emb = aggz/deg + bl2 + hr, writes it to d_out, then MLP.
// L1: 8n x 2c microtile (ch {l,l+64}, node half). L2+L3: R13 shape (balanced).
__global__ void __launch_bounds__(128, 6) classifier_kernel(
    const float* __restrict__ bl2,
    const float* __restrict__ Wc1, const float* __restrict__ bc1,
    const float* __restrict__ Wc2, const float* __restrict__ bc2,
    const float* __restrict__ Wc3, const float* __restrict__ bc3,
    float* __restrict__ emb, float* __restrict__ probs)
{
    __shared__ __align__(16) float s_e[TILE][OUT_C];       // 4 KB
    __shared__ __align__(16) float s_c1[TILE][HID];        // 8 KB
    __shared__ float s_rdeg[TILE];
    __shared__ float s_part[4][8];
    int t = threadIdx.x;
    int l = t & 63;                       // L1 ch pair {l, l+64}
    int ng = t >> 6;                      // L1 node half
    int c = t & 63;                       // L2 channel
    int nb = (t >> 6) * 8;                // L2 node group
    int wid = t >> 5;
    float b1a = __ldg(&bc1[l]);
    float b1b = __ldg(&bc1[l + 64]);
    float b2 = __ldg(&bc2[c]);
    float w3c = __ldg(&Wc3[c]);
    float b3 = __ldg(&bc3[0]);

    for (int tile = blockIdx.x; tile < NN / TILE; tile += gridDim.x) {
        int base = tile * TILE;
        __syncthreads();
        if (t < TILE) s_rdeg[t] = 1.0f / fmaxf(g_deg[base + t], 1.0f);
        __syncthreads();
        // stage emb = aggz/deg + bl2 + hr : 256 float4, 2 per thread; also write out
#pragma unroll
        for (int i = 0; i < 2; i++) {
            int f = t + 128 * i;
            int n = f >> 4, q = f & 15;
            float4 az = *(const float4*)(g_aggz + (size_t)(base + n) * OUT_C + q * 4);
            float4 hr = *(const float4*)(g_hr + (size_t)(base + n) * OUT_C + q * 4);
            float4 bv = __ldg((const float4*)(bl2 + q * 4));
            float r = s_rdeg[n];
            float4 e;
            e.x = az.x * r + bv.x + hr.x;
            e.y = az.y * r + bv.y + hr.y;
            e.z = az.z * r + bv.z + hr.z;
            e.w = az.w * r + bv.w + hr.w;
            *(float4*)&s_e[n][q * 4] = e;
            *(float4*)(emb + (size_t)(base + n) * OUT_C + q * 4) = e;
        }
        __syncthreads();

        // layer 1: c1 = relu(emb @ Wc1 + b1), 8 nodes x 2 hidden ch per thread
        {
            ull a0[8], a1[8];
#pragma unroll
            for (int n = 0; n < 8; n++) { a0[n] = 0; a1[n] = 0; }
            const float* s_row = &s_e[ng * 8][0];
#pragma unroll 4
            for (int ks = 0; ks < 16; ks++) {
                float wa = __ldg(&Wc1[(4 * ks + 0) * HID + l]);
                float wb = __ldg(&Wc1[(4 * ks + 1) * HID + l]);
                float wc = __ldg(&Wc1[(4 * ks + 2) * HID + l]);
                float wd = __ldg(&Wc1[(4 * ks + 3) * HID + l]);
                float va = __ldg(&Wc1[(4 * ks + 0) * HID + l + 64]);
                float vb = __ldg(&Wc1[(4 * ks + 1) * HID + l + 64]);
                float vc = __ldg(&Wc1[(4 * ks + 2) * HID + l + 64]);
                float vd = __ldg(&Wc1[(4 * ks + 3) * HID + l + 64]);
                ull wA0 = pack2(wa, wb), wB0 = pack2(wc, wd);
                ull wA1 = pack2(va, vb), wB1 = pack2(vc, vd);
#pragma unroll
                for (int n = 0; n < 8; n++) {
                    ulonglong2 v = *(const ulonglong2*)(s_row + n * OUT_C + ks * 4);
                    ffma2(a0[n], v.x, wA0); ffma2(a0[n], v.y, wB0);
                    ffma2(a1[n], v.x, wA1); ffma2(a1[n], v.y, wB1);
                }
            }
#pragma unroll
            for (int n = 0; n < 8; n++) {
                s_c1[ng * 8 + n][l]      = fmaxf(hadd2(a0[n]) + b1a, 0.f);
                s_c1[ng * 8 + n][l + 64] = fmaxf(hadd2(a1[n]) + b1b, 0.f);
            }
        }
        __syncthreads();

        // layer 2 + 3: thread (c, node-group), 8 nodes
        {
            ull p[8];
#pragma unroll
            for (int n = 0; n < 8; n++) p[n] = 0;
#pragma unroll 4
            for (int ks = 0; ks < 32; ks++) {
                float w0 = __ldg(&Wc2[(4 * ks + 0) * 64 + c]);
                float w1 = __ldg(&Wc2[(4 * ks + 1) * 64 + c]);
                float w2 = __ldg(&Wc2[(4 * ks + 2) * 64 + c]);
                float w3 = __ldg(&Wc2[(4 * ks + 3) * 64 + c]);
                ull wA = pack2(w0, w1), wB = pack2(w2, w3);
#pragma unroll
                for (int n = 0; n < 8; n++) {
                    ulonglong2 v = *(const ulonglong2*)&s_c1[nb + n][ks * 4];
                    ffma2(p[n], v.x, wA); ffma2(p[n], v.y, wB);
                }
            }
            float y[8];
#pragma unroll
            for (int n = 0; n < 8; n++)
                y[n] = fmaxf(hadd2(p[n]) + b2, 0.f) * w3c;
#pragma unroll
            for (int off = 16; off; off >>= 1) {
#pragma unroll
                for (int n = 0; n < 8; n++)
                    y[n] += __shfl_xor_sync(0xffffffffu, y[n], off);
            }
            if ((t & 31) == 0) {
#pragma unroll
                for (int n = 0; n < 8; n++) s_part[wid][n] = y[n];
            }
        }
        __syncthreads();
        if (t < TILE) {
            int n = t;
            float v = (n < 8) ? (s_part[0][n] + s_part[1][n])
                              : (s_part[2][n - 8] + s_part[3][n - 8]);
            v += b3;
            probs[base + n] = 1.0f / (1.0f + expf(-v));
        }
    }
}

// ---------------- launch ----------------
extern "C" void kernel_launch(void* const* d_in, const int* in_sizes, int n_in,
                              void* d_out, int out_size)
{
    const float* x   = (const float*)d_in[0];
    const void*  ei  = d_in[1];
    const float* Wl1 = (const float*)d_in[2];
    const float* bl1 = (const float*)d_in[3];
    const float* Wr1 = (const float*)d_in[4];
    const float* Wl2 = (const float*)d_in[5];
    const float* bl2 = (const float*)d_in[6];
    const float* Wr2 = (const float*)d_in[7];
    const float* Wc1 = (const float*)d_in[8];
    const float* bc1 = (const float*)d_in[9];
    const float* Wc2 = (const float*)d_in[10];
    const float* bc2 = (const float*)d_in[11];
    const float* Wc3 = (const float*)d_in[12];
    const float* bc3 = (const float*)d_in[13];
    int E = in_sizes[1] / 2;

    float* out   = (float*)d_out;
    float* emb   = out;                          // [NN, 64]
    float* probs = out + (size_t)NN * OUT_C;     // [NN, 1]

    detect_kernel<<<1, 32>>>(ei);
    zero_kernel<<<2048, 256>>>();
    conv1_agg_kernel<<<(E + 15) / 16, 256>>>(x, ei, E);
    fused_update_kernel<<<888, 128>>>(x, Wl1, bl1, Wr1, Wl2, Wr2);
    conv2_agg_kernel<<<(E + 15) / 16, 256>>>(ei, E);
    classifier_kernel<<<888, 128>>>(bl2, Wc1, bc1, Wc2, bc2, Wc3, bc3, emb, probs);
}